// round 9
// baseline (speedup 1.0000x reference)
#include <cuda_runtime.h>
#include <stdint.h>
#include <math.h>

#define NT 256

static const int TILES = 64;   // N*W = 4*16
static const int P     = 128;
static const int DD    = 96;
static const int SELK  = 100;
static const int GCHN  = 101;
static const int LCHN  = 80;
static const int SPLIT = 8;
static const int RPC   = 16;   // rows per CTA (2 per warp)

__device__ float g_M[DD*DD];    // W_q^T W_k
__device__ float g_c[DD];       // W_k^T b_q
__device__ float g_scale[GCHN]; // sigmoid(mb @ w_up^T + b_up)
__device__ float g_WoT[DD*DD];  // W_o transposed

__global__ void setup_kernel(const float* __restrict__ mb,
                             const float* __restrict__ w_up,
                             const float* __restrict__ b_up,
                             const float* __restrict__ w_q,
                             const float* __restrict__ b_q,
                             const float* __restrict__ w_k,
                             const float* __restrict__ w_o)
{
    int blk = blockIdx.x;
    int t   = threadIdx.x;
    if (blk < DD) {
        if (t < DD) {
            float acc = 0.f;
            #pragma unroll 8
            for (int k = 0; k < DD; k++)
                acc += w_q[k*DD + blk] * w_k[k*DD + t];
            g_M[blk*DD + t] = acc;
        }
    } else if (blk == DD) {
        if (t < DD) {
            float acc = 0.f;
            #pragma unroll 8
            for (int k = 0; k < DD; k++)
                acc += b_q[k] * w_k[k*DD + t];
            g_c[t] = acc;
        }
        if (t < GCHN) {
            float acc = b_up[t];
            #pragma unroll 8
            for (int l = 0; l < LCHN; l++)
                acc += w_up[t*LCHN + l] * mb[l];
            g_scale[t] = 1.f / (1.f + __expf(-acc));
        }
    } else {
        for (int idx = t; idx < DD*DD; idx += blockDim.x) {
            int k = idx / DD, d = idx - k*DD;
            g_WoT[k*DD + d] = w_o[d*DD + k];
        }
    }
}

// Vt element (d, i) lives at  d*128 + (i ^ (d & 31))  — conflict-free for:
//   broadcast reads, consecutive-i reads (lanes differ in i), and
//   row-major reads Vt[(lane+32k)][i] (bank = (i^lane)&31, all distinct).
__device__ __forceinline__ int vswz(int d, int i) { return d*128 + (i ^ (d & 31)); }

__global__ __launch_bounds__(NT, 4) void fused_kernel(
    const float* __restrict__ attn,
    const float* __restrict__ v,
    const float* __restrict__ b_o,
    float* __restrict__ out)
{
    extern __shared__ float sm[];
    float* Vt  = sm;              // [DD][128] swizzled V^T
    float* As  = Vt + DD*128;     // [RPC][DD]  A = V_rows @ M ; later reused as Os
    float* cvs = As + RPC*DD;     // [P]        c . V_i
    float* ssc = cvs + P;         // [104]      scale table

    const int tile = blockIdx.x / SPLIT;
    const int part = blockIdx.x % SPLIT;
    const int tid  = threadIdx.x;
    const int w    = tid >> 5;
    const int lane = tid & 31;
    const int row_base = part * RPC;
    const unsigned FULL = 0xffffffffu;

    // --- load V tile transposed+swizzled, float4 gmem reads ---
    const float4* vt4 = (const float4*)(v + (size_t)tile * P * DD);
    #pragma unroll
    for (int k = 0; k < (P*DD/4)/NT; k++) {     // 12 iterations
        int f = tid + k*NT;                      // float4 index
        int i = f / 24;                          // 24 float4 per row
        int d = (f - i*24) * 4;
        float4 val = vt4[f];
        Vt[vswz(d+0, i)] = val.x;
        Vt[vswz(d+1, i)] = val.y;
        Vt[vswz(d+2, i)] = val.z;
        Vt[vswz(d+3, i)] = val.w;
    }
    if (tid < GCHN) ssc[tid] = g_scale[tid];
    __syncthreads();

    // --- cvs[i] = sum_b c[b] * V[i][b] ---
    if (tid < P) {
        float acc = 0.f;
        #pragma unroll 8
        for (int b = 0; b < DD; b++) acc += g_c[b] * Vt[vswz(b, tid)];
        cvs[tid] = acc;
    }
    __syncthreads();

    // --- attn rows straight to registers as ordered uints (early LDG) ---
    const float* at = attn + (size_t)tile * P * P;
    uint32_t u[2][4];
    #pragma unroll
    for (int rr = 0; rr < 2; rr++) {
        const float* arow = at + (size_t)(row_base + 2*w + rr) * P;
        #pragma unroll
        for (int c = 0; c < 4; c++) {
            uint32_t s = __float_as_uint(arow[lane + 32*c]);
            u[rr][c] = s ^ ((uint32_t)((int32_t)s >> 31) | 0x80000000u);
        }
    }

    // --- Phase A: As[r][j] = sum_b V[row][b] * M[b][j] ---
    {
        float a0[2], a1[2], a2[2];
        #pragma unroll
        for (int rr = 0; rr < 2; rr++) { a0[rr]=0.f; a1[rr]=0.f; a2[rr]=0.f; }
        #pragma unroll 2
        for (int b = 0; b < DD; b++) {
            float m0 = g_M[b*DD + lane];
            float m1 = g_M[b*DD + lane + 32];
            float m2 = g_M[b*DD + lane + 64];
            #pragma unroll
            for (int rr = 0; rr < 2; rr++) {
                float vv = Vt[vswz(b, row_base + 2*w + rr)];
                a0[rr] += vv*m0; a1[rr] += vv*m1; a2[rr] += vv*m2;
            }
        }
        #pragma unroll
        for (int rr = 0; rr < 2; rr++) {
            As[(2*w+rr)*DD + lane]      = a0[rr];
            As[(2*w+rr)*DD + lane + 32] = a1[rr];
            As[(2*w+rr)*DD + lane + 64] = a2[rr];
        }
    }
    __syncwarp();

    // --- Top-100 per row via radix bisection on ordered-uint prefixes ---
    // tau = max prefix v with #{u >= v} >= 100  == the 100th-largest value.
    uint32_t pre[2] = {0u, 0u};
    #pragma unroll 1
    for (int bb = 31; bb >= 0; bb--) {
        uint32_t bit = 1u << bb;
        #pragma unroll
        for (int rr = 0; rr < 2; rr++) {
            uint32_t cand = pre[rr] | bit;
            int lc = (int)(u[rr][0] >= cand) + (int)(u[rr][1] >= cand)
                   + (int)(u[rr][2] >= cand) + (int)(u[rr][3] >= cand);
            int tot = __reduce_add_sync(FULL, lc);
            if (tot >= SELK) pre[rr] = cand;
        }
    }

    // --- selected mask + ascending-index rank -> scale value (registers) ---
    float sval[2][4];
    #pragma unroll
    for (int rr = 0; rr < 2; rr++) {
        bool s0 = u[rr][0] >= pre[rr];
        bool s1 = u[rr][1] >= pre[rr];
        bool s2 = u[rr][2] >= pre[rr];
        bool s3 = u[rr][3] >= pre[rr];
        unsigned m0 = __ballot_sync(FULL, s0);
        unsigned m1 = __ballot_sync(FULL, s1);
        unsigned m2 = __ballot_sync(FULL, s2);
        unsigned m3 = __ballot_sync(FULL, s3);
        unsigned lm = (1u << lane) - 1u;
        int t0 = __popc(m0), t1 = __popc(m1), t2 = __popc(m2);
        int r0 = 1 + __popc(m0 & lm);
        int r1 = 1 + t0 + __popc(m1 & lm);
        int r2 = 1 + t0 + t1 + __popc(m2 & lm);
        int r3 = 1 + t0 + t1 + t2 + __popc(m3 & lm);
        sval[rr][0] = s0 ? ssc[min(r0, SELK)] : 0.f;
        sval[rr][1] = s1 ? ssc[min(r1, SELK)] : 0.f;
        sval[rr][2] = s2 ? ssc[min(r2, SELK)] : 0.f;
        sval[rr][3] = s3 ? ssc[min(r3, SELK)] : 0.f;
    }

    // --- S = A . V^T, masked softmax -> combined weights (registers) ---
    const float s0c   = ssc[0];
    const float inv96 = 0.1020620726159657f;  // 1/sqrt(96)
    {
        float dot[2][4];
        #pragma unroll
        for (int rr = 0; rr < 2; rr++)
            #pragma unroll
            for (int c = 0; c < 4; c++) dot[rr][c] = 0.f;

        #pragma unroll 2
        for (int b = 0; b < DD; b++) {
            float v0 = Vt[vswz(b, lane)];
            float v1 = Vt[vswz(b, lane + 32)];
            float v2 = Vt[vswz(b, lane + 64)];
            float v3 = Vt[vswz(b, lane + 96)];
            #pragma unroll
            for (int rr = 0; rr < 2; rr++) {
                float av = As[(2*w+rr)*DD + b];
                dot[rr][0] += av*v0; dot[rr][1] += av*v1;
                dot[rr][2] += av*v2; dot[rr][3] += av*v3;
            }
        }

        float cv[4];
        #pragma unroll
        for (int c = 0; c < 4; c++) cv[c] = cvs[lane + 32*c];

        #pragma unroll
        for (int rr = 0; rr < 2; rr++) {
            float sc[4];
            float mx = -1e30f;
            #pragma unroll
            for (int c = 0; c < 4; c++) {
                float s = sval[rr][c] * (s0c * dot[rr][c] + cv[c]) * inv96;
                sc[c] = (sval[rr][c] != 0.f) ? s : -1e30f;
                mx = fmaxf(mx, sc[c]);
            }
            #pragma unroll
            for (int o = 16; o > 0; o >>= 1)
                mx = fmaxf(mx, __shfl_xor_sync(FULL, mx, o));
            float e[4], sum = 0.f;
            #pragma unroll
            for (int c = 0; c < 4; c++) { e[c] = __expf(sc[c] - mx); sum += e[c]; }
            #pragma unroll
            for (int o = 16; o > 0; o >>= 1)
                sum += __shfl_xor_sync(FULL, sum, o);
            float rs = 1.0f / sum;
            #pragma unroll
            for (int c = 0; c < 4; c++)
                sval[rr][c] = sval[rr][c] * e[c] * rs;   // final combined weight
        }
    }

    // --- Os = Wfull (16x128) @ V (128x96); weights broadcast via shfl ---
    float o0[2], o1[2], o2[2];
    #pragma unroll
    for (int rr = 0; rr < 2; rr++) { o0[rr]=0.f; o1[rr]=0.f; o2[rr]=0.f; }
    #pragma unroll 1
    for (int c4 = 0; c4 < 4; c4++) {
        #pragma unroll
        for (int l = 0; l < 32; l++) {
            int i  = c4*32 + l;
            int sx = i ^ lane;
            float v0 = Vt[(lane     )*128 + sx];
            float v1 = Vt[(lane + 32)*128 + sx];
            float v2 = Vt[(lane + 64)*128 + sx];
            #pragma unroll
            for (int rr = 0; rr < 2; rr++) {
                float wv = __shfl_sync(FULL, sval[rr][c4], l);
                o0[rr] += wv*v0; o1[rr] += wv*v1; o2[rr] += wv*v2;
            }
        }
    }
    __syncwarp();   // all lanes finished reading As (dot phase) before overwrite
    #pragma unroll
    for (int rr = 0; rr < 2; rr++) {
        As[(2*w+rr)*DD + lane]      = o0[rr];
        As[(2*w+rr)*DD + lane + 32] = o1[rr];
        As[(2*w+rr)*DD + lane + 64] = o2[rr];
    }
    __syncwarp();

    // --- final = Os @ W_o^T + b_o, write out ---
    {
        float f0[2], f1[2], f2[2];
        #pragma unroll
        for (int rr = 0; rr < 2; rr++) { f0[rr]=0.f; f1[rr]=0.f; f2[rr]=0.f; }
        #pragma unroll 2
        for (int t = 0; t < DD; t++) {
            float w0 = g_WoT[t*DD + lane];
            float w1 = g_WoT[t*DD + lane + 32];
            float w2 = g_WoT[t*DD + lane + 64];
            #pragma unroll
            for (int rr = 0; rr < 2; rr++) {
                float ov = As[(2*w+rr)*DD + t];
                f0[rr] += ov*w0; f1[rr] += ov*w1; f2[rr] += ov*w2;
            }
        }
        float bb0 = b_o[lane], bb1 = b_o[lane+32], bb2 = b_o[lane+64];
        #pragma unroll
        for (int rr = 0; rr < 2; rr++) {
            int arow = row_base + 2*w + rr;
            float* op = out + (size_t)tile*P*DD + (size_t)arow*DD;
            op[lane]      = f0[rr] + bb0;
            op[lane + 32] = f1[rr] + bb1;
            op[lane + 64] = f2[rr] + bb2;
        }
    }
}

extern "C" void kernel_launch(void* const* d_in, const int* in_sizes, int n_in,
                              void* d_out, int out_size)
{
    const float* attn = (const float*)d_in[0];
    const float* v    = (const float*)d_in[1];
    const float* mb   = (const float*)d_in[2];
    // d_in[3]=w_sub, d_in[4]=b_sub : dead code (softmax over size-1 axis)
    const float* w_up = (const float*)d_in[5];
    const float* b_up = (const float*)d_in[6];
    const float* w_q  = (const float*)d_in[7];
    const float* b_q  = (const float*)d_in[8];
    const float* w_k  = (const float*)d_in[9];
    // d_in[10]=b_k : row-constant in scores, cancels in softmax
    const float* w_o  = (const float*)d_in[11];
    const float* b_o  = (const float*)d_in[12];

    const size_t SMEM = (size_t)(DD*128 + RPC*DD + P + 104) * sizeof(float);
    cudaFuncSetAttribute(fused_kernel, cudaFuncAttributeMaxDynamicSharedMemorySize, (int)SMEM);

    setup_kernel<<<DD + 2, 128>>>(mb, w_up, b_up, w_q, b_q, w_k, w_o);
    fused_kernel<<<TILES * SPLIT, NT, SMEM>>>(attn, v, b_o, (float*)d_out);
}

// round 10
// speedup vs baseline: 1.2005x; 1.2005x over previous
#include <cuda_runtime.h>
#include <stdint.h>
#include <math.h>

#define NT 256

static const int TILES = 64;   // N*W = 4*16
static const int P     = 128;
static const int DD    = 96;
static const int SELK  = 100;
static const int GCHN  = 101;
static const int LCHN  = 80;
static const int SPLIT = 4;
static const int RPC   = 32;   // rows per CTA (4 per warp)
static const int VTS   = 129;  // Vt row stride: odd -> conflict-free, affine addressing

__device__ float g_M[DD*DD];    // W_q^T W_k
__device__ float g_c[DD];       // W_k^T b_q
__device__ float g_scale[GCHN]; // sigmoid(mb @ w_up^T + b_up)
__device__ float g_WoT[DD*DD];  // W_o transposed

__global__ void setup_kernel(const float* __restrict__ mb,
                             const float* __restrict__ w_up,
                             const float* __restrict__ b_up,
                             const float* __restrict__ w_q,
                             const float* __restrict__ b_q,
                             const float* __restrict__ w_k,
                             const float* __restrict__ w_o)
{
    int blk = blockIdx.x;
    int t   = threadIdx.x;
    if (blk < DD) {
        if (t < DD) {
            float acc = 0.f;
            #pragma unroll 8
            for (int k = 0; k < DD; k++)
                acc += w_q[k*DD + blk] * w_k[k*DD + t];
            g_M[blk*DD + t] = acc;
        }
    } else if (blk == DD) {
        if (t < DD) {
            float acc = 0.f;
            #pragma unroll 8
            for (int k = 0; k < DD; k++)
                acc += b_q[k] * w_k[k*DD + t];
            g_c[t] = acc;
        }
        if (t < GCHN) {
            float acc = b_up[t];
            #pragma unroll 8
            for (int l = 0; l < LCHN; l++)
                acc += w_up[t*LCHN + l] * mb[l];
            g_scale[t] = 1.f / (1.f + __expf(-acc));
        }
    } else {
        for (int idx = t; idx < DD*DD; idx += blockDim.x) {
            int k = idx / DD, d = idx - k*DD;
            g_WoT[k*DD + d] = w_o[d*DD + k];
        }
    }
}

__global__ __launch_bounds__(NT, 3) void fused_kernel(
    const float* __restrict__ attn,
    const float* __restrict__ v,
    const float* __restrict__ b_o,
    float* __restrict__ out)
{
    extern __shared__ float sm[];
    float* Vt  = sm;              // [DD][VTS] V^T, linear (affine LDS addressing)
    float* As  = Vt + DD*VTS;     // [RPC][DD]  A = V_rows @ M ; later reused as Os
    float* cvs = As + RPC*DD;     // [P]        c . V_i
    float* ssc = cvs + P;         // [104]      scale table

    const int tile = blockIdx.x / SPLIT;
    const int part = blockIdx.x % SPLIT;
    const int tid  = threadIdx.x;
    const int w    = tid >> 5;
    const int lane = tid & 31;
    const int row_base = part * RPC;
    const unsigned FULL = 0xffffffffu;

    // --- load V tile transposed, float4 gmem reads ---
    const float4* vt4 = (const float4*)(v + (size_t)tile * P * DD);
    #pragma unroll
    for (int k = 0; k < (P*DD/4)/NT; k++) {     // 12 iterations
        int f = tid + k*NT;                      // float4 index
        int i = f / 24;                          // 24 float4 per row
        int d = (f - i*24) * 4;
        float4 val = vt4[f];
        Vt[(d+0)*VTS + i] = val.x;
        Vt[(d+1)*VTS + i] = val.y;
        Vt[(d+2)*VTS + i] = val.z;
        Vt[(d+3)*VTS + i] = val.w;
    }
    if (tid < GCHN) ssc[tid] = g_scale[tid];
    __syncthreads();

    // --- cvs[i] = sum_b c[b] * V[i][b] ---
    if (tid < P) {
        float acc = 0.f;
        #pragma unroll 8
        for (int b = 0; b < DD; b++) acc += g_c[b] * Vt[b*VTS + tid];
        cvs[tid] = acc;
    }
    __syncthreads();

    // --- attn rows straight to registers as ordered uints (early LDG) ---
    const float* at = attn + (size_t)tile * P * P;
    uint32_t u[4][4];
    #pragma unroll
    for (int rr = 0; rr < 4; rr++) {
        const float* arow = at + (size_t)(row_base + 4*w + rr) * P;
        #pragma unroll
        for (int c = 0; c < 4; c++) {
            uint32_t s = __float_as_uint(arow[lane + 32*c]);
            u[rr][c] = s ^ ((uint32_t)((int32_t)s >> 31) | 0x80000000u);
        }
    }

    // --- Phase A: As[r][j] = sum_b V[row][b] * M[b][j] ---
    {
        float a0[4], a1[4], a2[4];
        #pragma unroll
        for (int rr = 0; rr < 4; rr++) { a0[rr]=0.f; a1[rr]=0.f; a2[rr]=0.f; }
        const float* vp = Vt + row_base + 4*w;
        const float* mp = g_M + lane;
        #pragma unroll 4
        for (int b = 0; b < DD; b++) {
            float m0 = mp[b*DD];
            float m1 = mp[b*DD + 32];
            float m2 = mp[b*DD + 64];
            #pragma unroll
            for (int rr = 0; rr < 4; rr++) {
                float vv = vp[b*VTS + rr];
                a0[rr] += vv*m0; a1[rr] += vv*m1; a2[rr] += vv*m2;
            }
        }
        #pragma unroll
        for (int rr = 0; rr < 4; rr++) {
            As[(4*w+rr)*DD + lane]      = a0[rr];
            As[(4*w+rr)*DD + lane + 32] = a1[rr];
            As[(4*w+rr)*DD + lane + 64] = a2[rr];
        }
    }
    __syncwarp();

    // --- Top-100 per row via radix bisection on ordered-uint prefixes ---
    // tau = max prefix v with #{u >= v} >= 100  == the 100th-largest value.
    uint32_t pre[4] = {0u, 0u, 0u, 0u};
    #pragma unroll 1
    for (int bb = 31; bb >= 0; bb--) {
        uint32_t bit = 1u << bb;
        #pragma unroll
        for (int rr = 0; rr < 4; rr++) {
            uint32_t cand = pre[rr] | bit;
            int lc = (int)(u[rr][0] >= cand) + (int)(u[rr][1] >= cand)
                   + (int)(u[rr][2] >= cand) + (int)(u[rr][3] >= cand);
            int tot = __reduce_add_sync(FULL, lc);
            if (tot >= SELK) pre[rr] = cand;
        }
    }

    // --- selected mask + ascending-index rank -> scale value (registers) ---
    float sval[4][4];
    #pragma unroll
    for (int rr = 0; rr < 4; rr++) {
        bool s0 = u[rr][0] >= pre[rr];
        bool s1 = u[rr][1] >= pre[rr];
        bool s2 = u[rr][2] >= pre[rr];
        bool s3 = u[rr][3] >= pre[rr];
        unsigned m0 = __ballot_sync(FULL, s0);
        unsigned m1 = __ballot_sync(FULL, s1);
        unsigned m2 = __ballot_sync(FULL, s2);
        unsigned m3 = __ballot_sync(FULL, s3);
        unsigned lm = (1u << lane) - 1u;
        int t0 = __popc(m0), t1 = __popc(m1), t2 = __popc(m2);
        int r0 = 1 + __popc(m0 & lm);
        int r1 = 1 + t0 + __popc(m1 & lm);
        int r2 = 1 + t0 + t1 + __popc(m2 & lm);
        int r3 = 1 + t0 + t1 + t2 + __popc(m3 & lm);
        sval[rr][0] = s0 ? ssc[min(r0, SELK)] : 0.f;
        sval[rr][1] = s1 ? ssc[min(r1, SELK)] : 0.f;
        sval[rr][2] = s2 ? ssc[min(r2, SELK)] : 0.f;
        sval[rr][3] = s3 ? ssc[min(r3, SELK)] : 0.f;
    }

    // --- S = A . V^T, masked softmax -> combined weights (registers) ---
    const float s0c   = ssc[0];
    const float inv96 = 0.1020620726159657f;  // 1/sqrt(96)
    {
        float dot[4][4];
        #pragma unroll
        for (int rr = 0; rr < 4; rr++)
            #pragma unroll
            for (int c = 0; c < 4; c++) dot[rr][c] = 0.f;

        const float* vp = Vt + lane;
        const float* ap = As + (4*w)*DD;
        #pragma unroll 4
        for (int b = 0; b < DD; b++) {
            float v0 = vp[b*VTS];
            float v1 = vp[b*VTS + 32];
            float v2 = vp[b*VTS + 64];
            float v3 = vp[b*VTS + 96];
            #pragma unroll
            for (int rr = 0; rr < 4; rr++) {
                float av = ap[rr*DD + b];
                dot[rr][0] += av*v0; dot[rr][1] += av*v1;
                dot[rr][2] += av*v2; dot[rr][3] += av*v3;
            }
        }

        float cv[4];
        #pragma unroll
        for (int c = 0; c < 4; c++) cv[c] = cvs[lane + 32*c];

        #pragma unroll
        for (int rr = 0; rr < 4; rr++) {
            float sc[4];
            float mx = -1e30f;
            #pragma unroll
            for (int c = 0; c < 4; c++) {
                float s = sval[rr][c] * (s0c * dot[rr][c] + cv[c]) * inv96;
                sc[c] = (sval[rr][c] != 0.f) ? s : -1e30f;
                mx = fmaxf(mx, sc[c]);
            }
            #pragma unroll
            for (int o = 16; o > 0; o >>= 1)
                mx = fmaxf(mx, __shfl_xor_sync(FULL, mx, o));
            float e[4], sum = 0.f;
            #pragma unroll
            for (int c = 0; c < 4; c++) { e[c] = __expf(sc[c] - mx); sum += e[c]; }
            #pragma unroll
            for (int o = 16; o > 0; o >>= 1)
                sum += __shfl_xor_sync(FULL, sum, o);
            float rs = 1.0f / sum;
            #pragma unroll
            for (int c = 0; c < 4; c++)
                sval[rr][c] = sval[rr][c] * e[c] * rs;   // final combined weight
        }
    }

    // --- Os = Wfull (32x128) @ V (128x96); weights broadcast via shfl ---
    float o0[4], o1[4], o2[4];
    #pragma unroll
    for (int rr = 0; rr < 4; rr++) { o0[rr]=0.f; o1[rr]=0.f; o2[rr]=0.f; }
    {
        const float* vp0 = Vt + (size_t)(lane     )*VTS;
        const float* vp1 = Vt + (size_t)(lane + 32)*VTS;
        const float* vp2 = Vt + (size_t)(lane + 64)*VTS;
        #pragma unroll 1
        for (int c4 = 0; c4 < 4; c4++) {
            #pragma unroll 4
            for (int l = 0; l < 32; l++) {
                int i = c4*32 + l;
                float v0 = vp0[i];
                float v1 = vp1[i];
                float v2 = vp2[i];
                #pragma unroll
                for (int rr = 0; rr < 4; rr++) {
                    float wv = __shfl_sync(FULL, sval[rr][c4], l);
                    o0[rr] += wv*v0; o1[rr] += wv*v1; o2[rr] += wv*v2;
                }
            }
        }
    }
    __syncwarp();   // all lanes finished reading As (dot phase) before overwrite
    #pragma unroll
    for (int rr = 0; rr < 4; rr++) {
        As[(4*w+rr)*DD + lane]      = o0[rr];
        As[(4*w+rr)*DD + lane + 32] = o1[rr];
        As[(4*w+rr)*DD + lane + 64] = o2[rr];
    }
    __syncwarp();

    // --- final = Os @ W_o^T + b_o, write out ---
    {
        float f0[4], f1[4], f2[4];
        #pragma unroll
        for (int rr = 0; rr < 4; rr++) { f0[rr]=0.f; f1[rr]=0.f; f2[rr]=0.f; }
        const float* op2 = As + (4*w)*DD;
        const float* wp  = g_WoT + lane;
        #pragma unroll 4
        for (int t = 0; t < DD; t++) {
            float w0 = wp[t*DD];
            float w1 = wp[t*DD + 32];
            float w2 = wp[t*DD + 64];
            #pragma unroll
            for (int rr = 0; rr < 4; rr++) {
                float ov = op2[rr*DD + t];
                f0[rr] += ov*w0; f1[rr] += ov*w1; f2[rr] += ov*w2;
            }
        }
        float bb0 = b_o[lane], bb1 = b_o[lane+32], bb2 = b_o[lane+64];
        #pragma unroll
        for (int rr = 0; rr < 4; rr++) {
            int arow = row_base + 4*w + rr;
            float* op = out + (size_t)tile*P*DD + (size_t)arow*DD;
            op[lane]      = f0[rr] + bb0;
            op[lane + 32] = f1[rr] + bb1;
            op[lane + 64] = f2[rr] + bb2;
        }
    }
}

extern "C" void kernel_launch(void* const* d_in, const int* in_sizes, int n_in,
                              void* d_out, int out_size)
{
    const float* attn = (const float*)d_in[0];
    const float* v    = (const float*)d_in[1];
    const float* mb   = (const float*)d_in[2];
    // d_in[3]=w_sub, d_in[4]=b_sub : dead code (softmax over size-1 axis)
    const float* w_up = (const float*)d_in[5];
    const float* b_up = (const float*)d_in[6];
    const float* w_q  = (const float*)d_in[7];
    const float* b_q  = (const float*)d_in[8];
    const float* w_k  = (const float*)d_in[9];
    // d_in[10]=b_k : row-constant in scores, cancels in softmax
    const float* w_o  = (const float*)d_in[11];
    const float* b_o  = (const float*)d_in[12];

    const size_t SMEM = (size_t)(DD*VTS + RPC*DD + P + 104) * sizeof(float);
    cudaFuncSetAttribute(fused_kernel, cudaFuncAttributeMaxDynamicSharedMemorySize, (int)SMEM);

    setup_kernel<<<DD + 2, 128>>>(mb, w_up, b_up, w_q, b_q, w_k, w_o);
    fused_kernel<<<TILES * SPLIT, NT, SMEM>>>(attn, v, b_o, (float*)d_out);
}